// round 3
// baseline (speedup 1.0000x reference)
#include <cuda_runtime.h>

// ---------------------------------------------------------------------------
// RgbNet, R3: two-kernel split for latency hiding.
//  K1 encode: one thread per (ray, sample, level) task (491K threads) ->
//             g_feat[120][16384] transposed in global (L2-resident).
//             Weight transpose for the MLP folded into the same launch.
//  K2 mlp:    block = 8 warps = one 32-ray group; warp computes 8 outputs
//             via 4 packed f32x2 accumulators. Weights via broadcast __ldg
//             (L1-resident), activations ping-pong in 16KB shared.
// ---------------------------------------------------------------------------

namespace {
constexpr int NRAYS   = 16384;
constexpr int NSAMP   = 300;
constexpr unsigned HSIZE = 1u << 19;
constexpr unsigned HMASK = HSIZE - 1u;
constexpr int WSTAGE  = 120 * 64 + 64 * 64 + 64 * 64;   // 15872
constexpr int ENC_THREADS = 256;
constexpr int ENC_BLOCKS  = (NRAYS * 30) / ENC_THREADS; // 1920
constexpr int MLP_THREADS = 256;                         // 8 warps
constexpr int MLP_BLOCKS  = NRAYS / 32;                  // 512
}

__device__ float g_Wt[WSTAGE];            // [W1t | W2t | W3t], each [k][o]
__device__ float g_feat[120 * NRAYS];     // [k][ray]

// ---- fp32x2 helpers -------------------------------------------------------
__device__ __forceinline__ unsigned long long pack2(float v) {
    unsigned long long r;
    asm("mov.b64 %0, {%1, %1};" : "=l"(r) : "f"(v));
    return r;
}
__device__ __forceinline__ float2 unpack2(unsigned long long v) {
    float2 r;
    asm("mov.b64 {%0, %1}, %2;" : "=f"(r.x), "=f"(r.y) : "l"(v));
    return r;
}
#define FMA2(acc, a, b) \
    asm("fma.rn.f32x2 %0, %1, %2, %0;" : "+l"(acc) : "l"(a), "l"(b))

// ===========================================================================
// Kernel 1: encoding (+ weight transpose piggybacked on the low blocks)
// ===========================================================================
__global__ __launch_bounds__(ENC_THREADS)
void encode_kernel(const float* __restrict__ x,       // [N,4]
                   const int*   __restrict__ ifirst,  // [N]
                   const float* __restrict__ emb,     // [6,2^19,4]
                   const float* __restrict__ W1,
                   const float* __restrict__ W2,
                   const float* __restrict__ W3)
{
    const int t = blockIdx.x * ENC_THREADS + threadIdx.x;

    // ---- piggyback: transpose W1/W2/W3 into g_Wt --------------------------
    if (t < WSTAGE) {
        float v;
        if (t < 7680) {
            int k = t >> 6, o = t & 63;
            v = W1[o * 120 + k];
        } else if (t < 11776) {
            int j = t - 7680; int k = j >> 6, o = j & 63;
            v = W2[o * 64 + k];
        } else {
            int j = t - 11776; int k = j >> 6, o = j & 63;
            v = W3[o * 64 + k];
        }
        g_Wt[t] = v;
    }

    // ---- main encoding task: t = combo*16384 + ray -------------------------
    const int ray   = t & (NRAYS - 1);
    const int combo = t >> 14;          // 0..29
    const int s = combo / 6;
    const int l = combo - s * 6;

    const float4 xr = __ldg(reinterpret_cast<const float4*>(x) + ray);
    int sc = __ldg(ifirst + ray) + s - 2;
    sc = sc < 0 ? 0 : (sc > NSAMP - 1 ? NSAMP - 1 : sc);
    const float tt  = (float)sc * (1.0f / 299.0f);
    const float omt = 1.0f - tt;
    const float px = xr.x * omt + xr.z * tt;
    const float py = xr.y * omt + xr.w * tt;
    const float pz = tt;

    const int   R  = 4 << l;
    const float fR = (float)R;
    const float fx = px * fR, fy = py * fR, fz = pz * fR;
    const float flx = floorf(fx), fly = floorf(fy), flz = floorf(fz);
    const int ix = (int)flx, iy = (int)fly, iz = (int)flz;
    const float wx = fx - flx, wy = fy - fly, wz = fz - flz;
    const int Rp1 = R + 1;

    const float4* __restrict__ tab =
        reinterpret_cast<const float4*>(emb) + (size_t)l * HSIZE;

    float ax = 0.f, ay = 0.f, az = 0.f, aw = 0.f;
    #pragma unroll
    for (int c = 0; c < 8; c++) {
        const int bx = (c >> 2) & 1, by = (c >> 1) & 1, bz = c & 1;
        int cx = ix + bx; cx = cx > R ? R : cx;
        int cy = iy + by; cy = cy > R ? R : cy;
        int cz = iz + bz; cz = cz > R ? R : cz;
        const unsigned id_dense =
            (unsigned)(cx + cy * Rp1 + cz * Rp1 * Rp1);
        const unsigned id_hash =
            ((unsigned)cx ^ ((unsigned)cy * 2654435761u)
                         ^ ((unsigned)cz * 805459861u)) & HMASK;
        const unsigned idx = (l == 5) ? id_hash : id_dense;
        const float4 e = __ldg(tab + idx);
        const float wgt = (bx ? wx : 1.0f - wx)
                        * (by ? wy : 1.0f - wy)
                        * (bz ? wz : 1.0f - wz);
        ax = fmaf(wgt, e.x, ax);
        ay = fmaf(wgt, e.y, ay);
        az = fmaf(wgt, e.z, az);
        aw = fmaf(wgt, e.w, aw);
    }

    const int kb = combo * 4;
    g_feat[(size_t)(kb + 0) * NRAYS + ray] = ax;
    g_feat[(size_t)(kb + 1) * NRAYS + ray] = ay;
    g_feat[(size_t)(kb + 2) * NRAYS + ray] = az;
    g_feat[(size_t)(kb + 3) * NRAYS + ray] = aw;
}

// ===========================================================================
// Kernel 2: MLP. Block = 8 warps = one 32-ray group; warp -> 8 outputs.
// ===========================================================================
__global__ __launch_bounds__(MLP_THREADS)
void mlp_kernel(const float* __restrict__ b1, const float* __restrict__ b2,
                const float* __restrict__ b3,
                const float* __restrict__ W4, const float* __restrict__ b4,
                float* __restrict__ out)
{
    __shared__ float hA[64 * 32];
    __shared__ float hB[64 * 32];

    const int lane  = threadIdx.x & 31;
    const int warp  = threadIdx.x >> 5;
    const int obase = warp * 8;                // 8 outputs per warp
    const int ray   = blockIdx.x * 32 + lane;

    unsigned long long acc[4];

    // ---------------- layer 1: 120 -> 64, fin from g_feat -------------------
    {
        const ulonglong2 bb0 = __ldg(reinterpret_cast<const ulonglong2*>(b1 + obase));
        const ulonglong2 bb1 = __ldg(reinterpret_cast<const ulonglong2*>(b1 + obase + 4));
        acc[0] = bb0.x; acc[1] = bb0.y; acc[2] = bb1.x; acc[3] = bb1.y;

        const float* __restrict__ Wt = g_Wt;   // W1t
        #pragma unroll 6
        for (int k = 0; k < 120; k++) {
            const float f = __ldg(&g_feat[(size_t)k * NRAYS + ray]);
            const unsigned long long ff = pack2(f);
            const ulonglong2 w01 =
                __ldg(reinterpret_cast<const ulonglong2*>(Wt + k * 64 + obase));
            const ulonglong2 w23 =
                __ldg(reinterpret_cast<const ulonglong2*>(Wt + k * 64 + obase + 4));
            FMA2(acc[0], ff, w01.x); FMA2(acc[1], ff, w01.y);
            FMA2(acc[2], ff, w23.x); FMA2(acc[3], ff, w23.y);
        }
        #pragma unroll
        for (int p = 0; p < 4; p++) {
            const float2 a = unpack2(acc[p]);
            hA[(obase + 2 * p)     * 32 + lane] = fmaxf(a.x, 0.0f);
            hA[(obase + 2 * p + 1) * 32 + lane] = fmaxf(a.y, 0.0f);
        }
    }
    __syncthreads();

    // ---------------- layer 2: 64 -> 64, hA -> hB ----------------------------
    {
        const ulonglong2 bb0 = __ldg(reinterpret_cast<const ulonglong2*>(b2 + obase));
        const ulonglong2 bb1 = __ldg(reinterpret_cast<const ulonglong2*>(b2 + obase + 4));
        acc[0] = bb0.x; acc[1] = bb0.y; acc[2] = bb1.x; acc[3] = bb1.y;

        const float* __restrict__ Wt = g_Wt + 7680;   // W2t
        #pragma unroll 8
        for (int k = 0; k < 64; k++) {
            const float f = hA[k * 32 + lane];
            const unsigned long long ff = pack2(f);
            const ulonglong2 w01 =
                __ldg(reinterpret_cast<const ulonglong2*>(Wt + k * 64 + obase));
            const ulonglong2 w23 =
                __ldg(reinterpret_cast<const ulonglong2*>(Wt + k * 64 + obase + 4));
            FMA2(acc[0], ff, w01.x); FMA2(acc[1], ff, w01.y);
            FMA2(acc[2], ff, w23.x); FMA2(acc[3], ff, w23.y);
        }
        #pragma unroll
        for (int p = 0; p < 4; p++) {
            const float2 a = unpack2(acc[p]);
            hB[(obase + 2 * p)     * 32 + lane] = fmaxf(a.x, 0.0f);
            hB[(obase + 2 * p + 1) * 32 + lane] = fmaxf(a.y, 0.0f);
        }
    }
    __syncthreads();

    // ---------------- layer 3: 64 -> 64, hB -> hA ----------------------------
    {
        const ulonglong2 bb0 = __ldg(reinterpret_cast<const ulonglong2*>(b3 + obase));
        const ulonglong2 bb1 = __ldg(reinterpret_cast<const ulonglong2*>(b3 + obase + 4));
        acc[0] = bb0.x; acc[1] = bb0.y; acc[2] = bb1.x; acc[3] = bb1.y;

        const float* __restrict__ Wt = g_Wt + 11776;  // W3t
        #pragma unroll 8
        for (int k = 0; k < 64; k++) {
            const float f = hB[k * 32 + lane];
            const unsigned long long ff = pack2(f);
            const ulonglong2 w01 =
                __ldg(reinterpret_cast<const ulonglong2*>(Wt + k * 64 + obase));
            const ulonglong2 w23 =
                __ldg(reinterpret_cast<const ulonglong2*>(Wt + k * 64 + obase + 4));
            FMA2(acc[0], ff, w01.x); FMA2(acc[1], ff, w01.y);
            FMA2(acc[2], ff, w23.x); FMA2(acc[3], ff, w23.y);
        }
        #pragma unroll
        for (int p = 0; p < 4; p++) {
            const float2 a = unpack2(acc[p]);
            hA[(obase + 2 * p)     * 32 + lane] = fmaxf(a.x, 0.0f);
            hA[(obase + 2 * p + 1) * 32 + lane] = fmaxf(a.y, 0.0f);
        }
    }
    __syncthreads();

    // ---------------- layer 4: 64 -> 3, warp 0 only --------------------------
    if (warp == 0) {
        float a0 = __ldg(b4 + 0), a1 = __ldg(b4 + 1), a2 = __ldg(b4 + 2);
        #pragma unroll 8
        for (int k = 0; k < 64; k++) {
            const float hv = hA[k * 32 + lane];
            a0 = fmaf(hv, __ldg(W4 + k),        a0);
            a1 = fmaf(hv, __ldg(W4 + 64 + k),   a1);
            a2 = fmaf(hv, __ldg(W4 + 128 + k),  a2);
        }
        float* o = out + (size_t)ray * 3;
        o[0] = a0; o[1] = a1; o[2] = a2;
    }
}

extern "C" void kernel_launch(void* const* d_in, const int* in_sizes, int n_in,
                              void* d_out, int out_size) {
    const float* x    = (const float*)d_in[0];
    const int*   idxf = (const int*)  d_in[1];
    const float* emb  = (const float*)d_in[2];
    const float* W1   = (const float*)d_in[3];
    const float* b1   = (const float*)d_in[4];
    const float* W2   = (const float*)d_in[5];
    const float* b2   = (const float*)d_in[6];
    const float* W3   = (const float*)d_in[7];
    const float* b3   = (const float*)d_in[8];
    const float* W4   = (const float*)d_in[9];
    const float* b4   = (const float*)d_in[10];
    float* out = (float*)d_out;

    encode_kernel<<<ENC_BLOCKS, ENC_THREADS>>>(x, idxf, emb, W1, W2, W3);
    mlp_kernel<<<MLP_BLOCKS, MLP_THREADS>>>(b1, b2, b3, W4, b4, out);
}

// round 4
// speedup vs baseline: 1.8656x; 1.8656x over previous
#include <cuda_runtime.h>

// ---------------------------------------------------------------------------
// RgbNet, R4: two kernels.
//  K1 encode: one thread per (ray,sample,level) -> g_feat[120][16384];
//             weight transpose piggybacked.
//  K2 mlp:    smem-resident transposed weights (staged coalesced), 8 warps /
//             64 rays per block; warp = 32 rays x 16 outputs via packed
//             f32x2 FMA; layer-1 feats prefetched 8-deep from global.
//             97KB smem -> 2 blocks/SM -> all 256 blocks in one wave.
// ---------------------------------------------------------------------------

namespace {
constexpr int NRAYS   = 16384;
constexpr int NSAMP   = 300;
constexpr unsigned HSIZE = 1u << 19;
constexpr unsigned HMASK = HSIZE - 1u;
constexpr int WSTAGE  = 120 * 64 + 64 * 64 + 64 * 64;   // 15872 floats
constexpr int ENC_THREADS = 256;
constexpr int ENC_BLOCKS  = (NRAYS * 30) / ENC_THREADS; // 1920

constexpr int MLP_THREADS = 256;     // 8 warps
constexpr int MLP_RPB     = 64;      // rays per block
constexpr int MLP_BLOCKS  = NRAYS / MLP_RPB;  // 256

// K2 shared layout (float offsets)
constexpr int OFF_W1T = 0;                    // [120][64]
constexpr int OFF_W2T = OFF_W1T + 120 * 64;   // [64][64]
constexpr int OFF_W3T = OFF_W2T + 64 * 64;    // [64][64]
constexpr int OFF_W4  = OFF_W3T + 64 * 64;    // [3][64]
constexpr int OFF_B1  = OFF_W4 + 192;
constexpr int OFF_B2  = OFF_B1 + 64;
constexpr int OFF_B3  = OFF_B2 + 64;
constexpr int OFF_B4  = OFF_B3 + 64;          // 4
constexpr int OFF_HA  = OFF_B4 + 4;           // [64][64]
constexpr int OFF_HB  = OFF_HA + 64 * 64;     // [64][64]
constexpr int SH_FLOATS = OFF_HB + 64 * 64;   // 24452 floats = 97808 B
}

__device__ float g_Wt[WSTAGE];            // [W1t | W2t | W3t], each [k][o]
__device__ float g_feat[120 * NRAYS];     // [k][ray]

// ---- fp32x2 helpers -------------------------------------------------------
__device__ __forceinline__ unsigned long long pack2(float v) {
    unsigned long long r;
    asm("mov.b64 %0, {%1, %1};" : "=l"(r) : "f"(v));
    return r;
}
__device__ __forceinline__ float2 unpack2(unsigned long long v) {
    float2 r;
    asm("mov.b64 {%0, %1}, %2;" : "=f"(r.x), "=f"(r.y) : "l"(v));
    return r;
}
#define FMA2(acc, a, b) \
    asm("fma.rn.f32x2 %0, %1, %2, %0;" : "+l"(acc) : "l"(a), "l"(b))

// ===========================================================================
// Kernel 1: encoding (+ weight transpose piggybacked)
// ===========================================================================
__global__ __launch_bounds__(ENC_THREADS)
void encode_kernel(const float* __restrict__ x,       // [N,4]
                   const int*   __restrict__ ifirst,  // [N]
                   const float* __restrict__ emb,     // [6,2^19,4]
                   const float* __restrict__ W1,
                   const float* __restrict__ W2,
                   const float* __restrict__ W3)
{
    const int t = blockIdx.x * ENC_THREADS + threadIdx.x;

    if (t < WSTAGE) {
        float v;
        if (t < 7680) {
            int k = t >> 6, o = t & 63;
            v = W1[o * 120 + k];
        } else if (t < 11776) {
            int j = t - 7680; int k = j >> 6, o = j & 63;
            v = W2[o * 64 + k];
        } else {
            int j = t - 11776; int k = j >> 6, o = j & 63;
            v = W3[o * 64 + k];
        }
        g_Wt[t] = v;
    }

    const int ray   = t & (NRAYS - 1);
    const int combo = t >> 14;          // 0..29
    const int s = combo / 6;
    const int l = combo - s * 6;

    const float4 xr = __ldg(reinterpret_cast<const float4*>(x) + ray);
    int sc = __ldg(ifirst + ray) + s - 2;
    sc = sc < 0 ? 0 : (sc > NSAMP - 1 ? NSAMP - 1 : sc);
    const float tt  = (float)sc * (1.0f / 299.0f);
    const float omt = 1.0f - tt;
    const float px = xr.x * omt + xr.z * tt;
    const float py = xr.y * omt + xr.w * tt;
    const float pz = tt;

    const int   R  = 4 << l;
    const float fR = (float)R;
    const float fx = px * fR, fy = py * fR, fz = pz * fR;
    const float flx = floorf(fx), fly = floorf(fy), flz = floorf(fz);
    const int ix = (int)flx, iy = (int)fly, iz = (int)flz;
    const float wx = fx - flx, wy = fy - fly, wz = fz - flz;
    const int Rp1 = R + 1;

    const float4* __restrict__ tab =
        reinterpret_cast<const float4*>(emb) + (size_t)l * HSIZE;

    float ax = 0.f, ay = 0.f, az = 0.f, aw = 0.f;
    #pragma unroll
    for (int c = 0; c < 8; c++) {
        const int bx = (c >> 2) & 1, by = (c >> 1) & 1, bz = c & 1;
        int cx = ix + bx; cx = cx > R ? R : cx;
        int cy = iy + by; cy = cy > R ? R : cy;
        int cz = iz + bz; cz = cz > R ? R : cz;
        const unsigned id_dense =
            (unsigned)(cx + cy * Rp1 + cz * Rp1 * Rp1);
        const unsigned id_hash =
            ((unsigned)cx ^ ((unsigned)cy * 2654435761u)
                         ^ ((unsigned)cz * 805459861u)) & HMASK;
        const unsigned idx = (l == 5) ? id_hash : id_dense;
        const float4 e = __ldg(tab + idx);
        const float wgt = (bx ? wx : 1.0f - wx)
                        * (by ? wy : 1.0f - wy)
                        * (bz ? wz : 1.0f - wz);
        ax = fmaf(wgt, e.x, ax);
        ay = fmaf(wgt, e.y, ay);
        az = fmaf(wgt, e.z, az);
        aw = fmaf(wgt, e.w, aw);
    }

    const int kb = combo * 4;
    g_feat[(size_t)(kb + 0) * NRAYS + ray] = ax;
    g_feat[(size_t)(kb + 1) * NRAYS + ray] = ay;
    g_feat[(size_t)(kb + 2) * NRAYS + ray] = az;
    g_feat[(size_t)(kb + 3) * NRAYS + ray] = aw;
}

// ===========================================================================
// Kernel 2: MLP
// ===========================================================================

// hidden layer (64 -> 64): acts from smem
__device__ __forceinline__ void layer_hidden(const float* __restrict__ Wt,
                                             const float* __restrict__ bs,
                                             const float* __restrict__ actIn,
                                             float*       __restrict__ actOut,
                                             int obase, int ridx) {
    unsigned long long acc[8];
    const unsigned long long* bp =
        reinterpret_cast<const unsigned long long*>(bs + obase);
    #pragma unroll
    for (int p = 0; p < 8; p++) acc[p] = bp[p];

    #pragma unroll 4
    for (int k = 0; k < 64; k++) {
        const float f = actIn[k * 64 + ridx];
        const unsigned long long ff = pack2(f);
        const ulonglong2* wp =
            reinterpret_cast<const ulonglong2*>(Wt + k * 64 + obase);
        const ulonglong2 w0 = wp[0], w1 = wp[1], w2 = wp[2], w3 = wp[3];
        FMA2(acc[0], ff, w0.x); FMA2(acc[1], ff, w0.y);
        FMA2(acc[2], ff, w1.x); FMA2(acc[3], ff, w1.y);
        FMA2(acc[4], ff, w2.x); FMA2(acc[5], ff, w2.y);
        FMA2(acc[6], ff, w3.x); FMA2(acc[7], ff, w3.y);
    }
    #pragma unroll
    for (int p = 0; p < 8; p++) {
        const float2 a = unpack2(acc[p]);
        actOut[(obase + 2 * p)     * 64 + ridx] = fmaxf(a.x, 0.0f);
        actOut[(obase + 2 * p + 1) * 64 + ridx] = fmaxf(a.y, 0.0f);
    }
}

__global__ __launch_bounds__(MLP_THREADS, 2)
void mlp_kernel(const float* __restrict__ b1, const float* __restrict__ b2,
                const float* __restrict__ b3,
                const float* __restrict__ W4, const float* __restrict__ b4,
                float* __restrict__ out)
{
    extern __shared__ float sh[];
    const int tid = threadIdx.x;

    // ---- stage pre-transposed weights: float4 coalesced, conflict-free ----
    {
        const float4* src = reinterpret_cast<const float4*>(g_Wt);
        float4*       dst = reinterpret_cast<float4*>(sh);
        #pragma unroll
        for (int i = tid; i < WSTAGE / 4; i += MLP_THREADS) dst[i] = src[i];
    }
    if (tid < 192) sh[OFF_W4 + tid] = __ldg(W4 + tid);
    if (tid < 64) {
        sh[OFF_B1 + tid] = __ldg(b1 + tid);
        sh[OFF_B2 + tid] = __ldg(b2 + tid);
        sh[OFF_B3 + tid] = __ldg(b3 + tid);
    }
    if (tid < 4) sh[OFF_B4 + tid] = (tid < 3) ? __ldg(b4 + tid) : 0.0f;
    __syncthreads();

    const int lane  = tid & 31;
    const int warp  = tid >> 5;
    const int obase = (warp & 3) * 16;             // output chunk
    const int ridx  = (warp >> 2) * 32 + lane;     // ray within block (0..63)
    const int ray   = blockIdx.x * MLP_RPB + ridx;

    float* hA = sh + OFF_HA;
    float* hB = sh + OFF_HB;

    // ---------------- layer 1: 120 -> 64, feats from g_feat (prefetched) ----
    {
        unsigned long long acc[8];
        const unsigned long long* bp =
            reinterpret_cast<const unsigned long long*>(sh + OFF_B1 + obase);
        #pragma unroll
        for (int p = 0; p < 8; p++) acc[p] = bp[p];

        const float* __restrict__ Wt = sh + OFF_W1T;

        float fbuf[8];
        #pragma unroll
        for (int j = 0; j < 8; j++)
            fbuf[j] = __ldg(&g_feat[(size_t)j * NRAYS + ray]);

        for (int kb = 0; kb < 120; kb += 8) {
            float fc[8];
            #pragma unroll
            for (int j = 0; j < 8; j++) fc[j] = fbuf[j];
            if (kb + 8 < 120) {
                #pragma unroll
                for (int j = 0; j < 8; j++)
                    fbuf[j] = __ldg(&g_feat[(size_t)(kb + 8 + j) * NRAYS + ray]);
            }
            #pragma unroll
            for (int j = 0; j < 8; j++) {
                const unsigned long long ff = pack2(fc[j]);
                const ulonglong2* wp = reinterpret_cast<const ulonglong2*>(
                    Wt + (kb + j) * 64 + obase);
                const ulonglong2 w0 = wp[0], w1 = wp[1], w2 = wp[2], w3 = wp[3];
                FMA2(acc[0], ff, w0.x); FMA2(acc[1], ff, w0.y);
                FMA2(acc[2], ff, w1.x); FMA2(acc[3], ff, w1.y);
                FMA2(acc[4], ff, w2.x); FMA2(acc[5], ff, w2.y);
                FMA2(acc[6], ff, w3.x); FMA2(acc[7], ff, w3.y);
            }
        }
        #pragma unroll
        for (int p = 0; p < 8; p++) {
            const float2 a = unpack2(acc[p]);
            hA[(obase + 2 * p)     * 64 + ridx] = fmaxf(a.x, 0.0f);
            hA[(obase + 2 * p + 1) * 64 + ridx] = fmaxf(a.y, 0.0f);
        }
    }
    __syncthreads();

    // ---------------- layer 2: hA -> hB --------------------------------------
    layer_hidden(sh + OFF_W2T, sh + OFF_B2, hA, hB, obase, ridx);
    __syncthreads();

    // ---------------- layer 3: hB -> hA --------------------------------------
    layer_hidden(sh + OFF_W3T, sh + OFF_B3, hB, hA, obase, ridx);
    __syncthreads();

    // ---------------- layer 4: 64 -> 3, threads 0..63 ------------------------
    if (tid < MLP_RPB) {
        const float* W4s = sh + OFF_W4;
        float a0 = sh[OFF_B4 + 0], a1 = sh[OFF_B4 + 1], a2 = sh[OFF_B4 + 2];
        #pragma unroll 8
        for (int k = 0; k < 64; k++) {
            const float hv = hA[k * 64 + tid];
            a0 = fmaf(hv, W4s[k],       a0);
            a1 = fmaf(hv, W4s[64 + k],  a1);
            a2 = fmaf(hv, W4s[128 + k], a2);
        }
        float* o = out + (size_t)(blockIdx.x * MLP_RPB + tid) * 3;
        o[0] = a0; o[1] = a1; o[2] = a2;
    }
}

extern "C" void kernel_launch(void* const* d_in, const int* in_sizes, int n_in,
                              void* d_out, int out_size) {
    const float* x    = (const float*)d_in[0];
    const int*   idxf = (const int*)  d_in[1];
    const float* emb  = (const float*)d_in[2];
    const float* W1   = (const float*)d_in[3];
    const float* b1   = (const float*)d_in[4];
    const float* W2   = (const float*)d_in[5];
    const float* b2   = (const float*)d_in[6];
    const float* W3   = (const float*)d_in[7];
    const float* b3   = (const float*)d_in[8];
    const float* W4   = (const float*)d_in[9];
    const float* b4   = (const float*)d_in[10];
    float* out = (float*)d_out;

    encode_kernel<<<ENC_BLOCKS, ENC_THREADS>>>(x, idxf, emb, W1, W2, W3);

    const size_t shbytes = (size_t)SH_FLOATS * sizeof(float);   // 97808 B
    cudaFuncSetAttribute(mlp_kernel,
                         cudaFuncAttributeMaxDynamicSharedMemorySize,
                         (int)shbytes);
    mlp_kernel<<<MLP_BLOCKS, MLP_THREADS, shbytes>>>(b1, b2, b3, W4, b4, out);
}

// round 5
// speedup vs baseline: 2.0559x; 1.1020x over previous
#include <cuda_runtime.h>

// ---------------------------------------------------------------------------
// RgbNet, R5.
//  K1 encode: one thread per (ray, level); loops 5 samples with a register
//             corner cache (same cell -> skip the 8 gathers). Weight
//             transpose piggybacked. Writes g_feat[120][16384].
//  K2 mlp:    512 threads / 64 rays per block, 16 warps; warp = 8 outputs x
//             32 rays (4 f32x2 accumulators) -> 4096 warps total (~28/SM).
//             Weights in smem (LDS.128 broadcast), acts ping-pong in smem.
// ---------------------------------------------------------------------------

namespace {
constexpr int NRAYS   = 16384;
constexpr int NSAMP   = 300;
constexpr unsigned HSIZE = 1u << 19;
constexpr unsigned HMASK = HSIZE - 1u;
constexpr int WSTAGE  = 120 * 64 + 64 * 64 + 64 * 64;   // 15872 floats

constexpr int ENC_THREADS = 256;
constexpr int ENC_TASKS   = NRAYS * 6;                   // (ray, level)
constexpr int ENC_BLOCKS  = ENC_TASKS / ENC_THREADS;     // 384

constexpr int MLP_THREADS = 512;     // 16 warps
constexpr int MLP_RPB     = 64;      // rays per block
constexpr int MLP_BLOCKS  = NRAYS / MLP_RPB;             // 256

// K2 shared layout (float offsets)
constexpr int OFF_W1T = 0;                    // [120][64]
constexpr int OFF_W2T = OFF_W1T + 120 * 64;   // [64][64]
constexpr int OFF_W3T = OFF_W2T + 64 * 64;    // [64][64]
constexpr int OFF_W4  = OFF_W3T + 64 * 64;    // [3][64]
constexpr int OFF_B1  = OFF_W4 + 192;
constexpr int OFF_B2  = OFF_B1 + 64;
constexpr int OFF_B3  = OFF_B2 + 64;
constexpr int OFF_B4  = OFF_B3 + 64;          // 4
constexpr int OFF_HA  = OFF_B4 + 4;           // [64][64]
constexpr int OFF_HB  = OFF_HA + 64 * 64;     // [64][64]
constexpr int SH_FLOATS = OFF_HB + 64 * 64;   // 24452 floats = 97808 B
}

__device__ float g_Wt[WSTAGE];            // [W1t | W2t | W3t], each [k][o]
__device__ float g_feat[120 * NRAYS];     // [k][ray]

// ---- fp32x2 helpers -------------------------------------------------------
__device__ __forceinline__ unsigned long long pack2(float v) {
    unsigned long long r;
    asm("mov.b64 %0, {%1, %1};" : "=l"(r) : "f"(v));
    return r;
}
__device__ __forceinline__ float2 unpack2(unsigned long long v) {
    float2 r;
    asm("mov.b64 {%0, %1}, %2;" : "=f"(r.x), "=f"(r.y) : "l"(v));
    return r;
}
#define FMA2(acc, a, b) \
    asm("fma.rn.f32x2 %0, %1, %2, %0;" : "+l"(acc) : "l"(a), "l"(b))

// ===========================================================================
// Kernel 1: encoding, thread per (ray, level), 5 samples with corner cache
// ===========================================================================
__global__ __launch_bounds__(ENC_THREADS)
void encode_kernel(const float* __restrict__ x,       // [N,4]
                   const int*   __restrict__ ifirst,  // [N]
                   const float* __restrict__ emb,     // [6,2^19,4]
                   const float* __restrict__ W1,
                   const float* __restrict__ W2,
                   const float* __restrict__ W3)
{
    const int t = blockIdx.x * ENC_THREADS + threadIdx.x;

    // ---- piggyback: transpose W1/W2/W3 into g_Wt ---------------------------
    if (t < WSTAGE) {
        float v;
        if (t < 7680) {
            int k = t >> 6, o = t & 63;
            v = W1[o * 120 + k];
        } else if (t < 11776) {
            int j = t - 7680; int k = j >> 6, o = j & 63;
            v = W2[o * 64 + k];
        } else {
            int j = t - 11776; int k = j >> 6, o = j & 63;
            v = W3[o * 64 + k];
        }
        g_Wt[t] = v;
    }

    const int ray = t & (NRAYS - 1);
    const int l   = t >> 14;                 // 0..5, uniform per warp

    const float4 xr  = __ldg(reinterpret_cast<const float4*>(x) + ray);
    const int    if0 = __ldg(ifirst + ray);

    const int   R   = 4 << l;
    const float fR  = (float)R;
    const int   Rp1 = R + 1;
    const float4* __restrict__ tab =
        reinterpret_cast<const float4*>(emb) + (size_t)l * HSIZE;

    int    prev_key = -1;
    float4 cc[8];                            // cached corner embeddings

    #pragma unroll
    for (int s = 0; s < 5; s++) {
        int sc = if0 + s - 2;
        sc = sc < 0 ? 0 : (sc > NSAMP - 1 ? NSAMP - 1 : sc);
        const float tt  = (float)sc * (1.0f / 299.0f);
        const float omt = 1.0f - tt;
        const float px = xr.x * omt + xr.z * tt;
        const float py = xr.y * omt + xr.w * tt;
        const float pz = tt;

        const float fx = px * fR, fy = py * fR, fz = pz * fR;
        const float flx = floorf(fx), fly = floorf(fy), flz = floorf(fz);
        const int ix = (int)flx, iy = (int)fly, iz = (int)flz;
        const float wx = fx - flx, wy = fy - fly, wz = fz - flz;

        const int key = ix | (iy << 10) | (iz << 20);
        if (key != prev_key) {
            prev_key = key;
            #pragma unroll
            for (int c = 0; c < 8; c++) {
                const int bx = (c >> 2) & 1, by = (c >> 1) & 1, bz = c & 1;
                int cx = ix + bx; cx = cx > R ? R : cx;
                int cy = iy + by; cy = cy > R ? R : cy;
                int cz = iz + bz; cz = cz > R ? R : cz;
                const unsigned id_dense =
                    (unsigned)(cx + cy * Rp1 + cz * Rp1 * Rp1);
                const unsigned id_hash =
                    ((unsigned)cx ^ ((unsigned)cy * 2654435761u)
                                 ^ ((unsigned)cz * 805459861u)) & HMASK;
                const unsigned idx = (l == 5) ? id_hash : id_dense;
                cc[c] = __ldg(tab + idx);
            }
        }

        float ax = 0.f, ay = 0.f, az = 0.f, aw = 0.f;
        #pragma unroll
        for (int c = 0; c < 8; c++) {
            const int bx = (c >> 2) & 1, by = (c >> 1) & 1, bz = c & 1;
            const float wgt = (bx ? wx : 1.0f - wx)
                            * (by ? wy : 1.0f - wy)
                            * (bz ? wz : 1.0f - wz);
            ax = fmaf(wgt, cc[c].x, ax);
            ay = fmaf(wgt, cc[c].y, ay);
            az = fmaf(wgt, cc[c].z, az);
            aw = fmaf(wgt, cc[c].w, aw);
        }

        const int kb = (s * 6 + l) * 4;
        g_feat[(size_t)(kb + 0) * NRAYS + ray] = ax;
        g_feat[(size_t)(kb + 1) * NRAYS + ray] = ay;
        g_feat[(size_t)(kb + 2) * NRAYS + ray] = az;
        g_feat[(size_t)(kb + 3) * NRAYS + ray] = aw;
    }
}

// ===========================================================================
// Kernel 2: MLP. 16 warps; warp = 8 outputs x 32 rays.
// ===========================================================================

__device__ __forceinline__ void layer_hidden8(const float* __restrict__ Wt,
                                              const float* __restrict__ bs,
                                              const float* __restrict__ actIn,
                                              float*       __restrict__ actOut,
                                              int obase, int ridx) {
    unsigned long long acc[4];
    {
        const ulonglong2* bp =
            reinterpret_cast<const ulonglong2*>(bs + obase);   // 32B aligned
        const ulonglong2 b0 = bp[0], b1 = bp[1];
        acc[0] = b0.x; acc[1] = b0.y; acc[2] = b1.x; acc[3] = b1.y;
    }
    #pragma unroll 4
    for (int k = 0; k < 64; k++) {
        const float f = actIn[k * 64 + ridx];
        const unsigned long long ff = pack2(f);
        const ulonglong2* wp =
            reinterpret_cast<const ulonglong2*>(Wt + k * 64 + obase);
        const ulonglong2 w0 = wp[0], w1 = wp[1];
        FMA2(acc[0], ff, w0.x); FMA2(acc[1], ff, w0.y);
        FMA2(acc[2], ff, w1.x); FMA2(acc[3], ff, w1.y);
    }
    #pragma unroll
    for (int p = 0; p < 4; p++) {
        const float2 a = unpack2(acc[p]);
        actOut[(obase + 2 * p)     * 64 + ridx] = fmaxf(a.x, 0.0f);
        actOut[(obase + 2 * p + 1) * 64 + ridx] = fmaxf(a.y, 0.0f);
    }
}

__global__ __launch_bounds__(MLP_THREADS, 2)
void mlp_kernel(const float* __restrict__ b1, const float* __restrict__ b2,
                const float* __restrict__ b3,
                const float* __restrict__ W4, const float* __restrict__ b4,
                float* __restrict__ out)
{
    extern __shared__ float sh[];
    const int tid = threadIdx.x;

    // ---- stage pre-transposed weights: float4 coalesced, conflict-free ----
    {
        const float4* src = reinterpret_cast<const float4*>(g_Wt);
        float4*       dst = reinterpret_cast<float4*>(sh);
        #pragma unroll
        for (int i = tid; i < WSTAGE / 4; i += MLP_THREADS) dst[i] = src[i];
    }
    if (tid < 192) sh[OFF_W4 + tid] = __ldg(W4 + tid);
    if (tid < 64) {
        sh[OFF_B1 + tid] = __ldg(b1 + tid);
        sh[OFF_B2 + tid] = __ldg(b2 + tid);
        sh[OFF_B3 + tid] = __ldg(b3 + tid);
    }
    if (tid < 4) sh[OFF_B4 + tid] = (tid < 3) ? __ldg(b4 + tid) : 0.0f;
    __syncthreads();

    const int lane  = tid & 31;
    const int warp  = tid >> 5;                    // 0..15
    const int obase = (warp & 7) * 8;              // 8-output chunk
    const int ridx  = (warp >> 3) * 32 + lane;     // ray within block (0..63)
    const int ray   = blockIdx.x * MLP_RPB + ridx;

    float* hA = sh + OFF_HA;
    float* hB = sh + OFF_HB;

    // ---------------- layer 1: 120 -> 64, feats from g_feat (prefetched) ----
    {
        unsigned long long acc[4];
        {
            const ulonglong2* bp =
                reinterpret_cast<const ulonglong2*>(sh + OFF_B1 + obase);
            const ulonglong2 b0 = bp[0], bb1 = bp[1];
            acc[0] = b0.x; acc[1] = b0.y; acc[2] = bb1.x; acc[3] = bb1.y;
        }
        const float* __restrict__ Wt = sh + OFF_W1T;

        float fbuf[8];
        #pragma unroll
        for (int j = 0; j < 8; j++)
            fbuf[j] = __ldg(&g_feat[(size_t)j * NRAYS + ray]);

        for (int kb = 0; kb < 120; kb += 8) {
            float fc[8];
            #pragma unroll
            for (int j = 0; j < 8; j++) fc[j] = fbuf[j];
            if (kb + 8 < 120) {
                #pragma unroll
                for (int j = 0; j < 8; j++)
                    fbuf[j] = __ldg(&g_feat[(size_t)(kb + 8 + j) * NRAYS + ray]);
            }
            #pragma unroll
            for (int j = 0; j < 8; j++) {
                const unsigned long long ff = pack2(fc[j]);
                const ulonglong2* wp = reinterpret_cast<const ulonglong2*>(
                    Wt + (kb + j) * 64 + obase);
                const ulonglong2 w0 = wp[0], w1 = wp[1];
                FMA2(acc[0], ff, w0.x); FMA2(acc[1], ff, w0.y);
                FMA2(acc[2], ff, w1.x); FMA2(acc[3], ff, w1.y);
            }
        }
        #pragma unroll
        for (int p = 0; p < 4; p++) {
            const float2 a = unpack2(acc[p]);
            hA[(obase + 2 * p)     * 64 + ridx] = fmaxf(a.x, 0.0f);
            hA[(obase + 2 * p + 1) * 64 + ridx] = fmaxf(a.y, 0.0f);
        }
    }
    __syncthreads();

    // ---------------- layer 2: hA -> hB --------------------------------------
    layer_hidden8(sh + OFF_W2T, sh + OFF_B2, hA, hB, obase, ridx);
    __syncthreads();

    // ---------------- layer 3: hB -> hA --------------------------------------
    layer_hidden8(sh + OFF_W3T, sh + OFF_B3, hB, hA, obase, ridx);
    __syncthreads();

    // ---------------- layer 4: 64 -> 3, threads 0..63 ------------------------
    if (tid < MLP_RPB) {
        const float* W4s = sh + OFF_W4;
        float a0 = sh[OFF_B4 + 0], a1 = sh[OFF_B4 + 1], a2 = sh[OFF_B4 + 2];
        #pragma unroll 8
        for (int k = 0; k < 64; k++) {
            const float hv = hA[k * 64 + tid];
            a0 = fmaf(hv, W4s[k],       a0);
            a1 = fmaf(hv, W4s[64 + k],  a1);
            a2 = fmaf(hv, W4s[128 + k], a2);
        }
        float* o = out + (size_t)(blockIdx.x * MLP_RPB + tid) * 3;
        o[0] = a0; o[1] = a1; o[2] = a2;
    }
}

extern "C" void kernel_launch(void* const* d_in, const int* in_sizes, int n_in,
                              void* d_out, int out_size) {
    const float* x    = (const float*)d_in[0];
    const int*   idxf = (const int*)  d_in[1];
    const float* emb  = (const float*)d_in[2];
    const float* W1   = (const float*)d_in[3];
    const float* b1   = (const float*)d_in[4];
    const float* W2   = (const float*)d_in[5];
    const float* b2   = (const float*)d_in[6];
    const float* W3   = (const float*)d_in[7];
    const float* b3   = (const float*)d_in[8];
    const float* W4   = (const float*)d_in[9];
    const float* b4   = (const float*)d_in[10];
    float* out = (float*)d_out;

    encode_kernel<<<ENC_BLOCKS, ENC_THREADS>>>(x, idxf, emb, W1, W2, W3);

    const size_t shbytes = (size_t)SH_FLOATS * sizeof(float);   // 97808 B
    cudaFuncSetAttribute(mlp_kernel,
                         cudaFuncAttributeMaxDynamicSharedMemorySize,
                         (int)shbytes);
    mlp_kernel<<<MLP_BLOCKS, MLP_THREADS, shbytes>>>(b1, b2, b3, W4, b4, out);
}

// round 6
// speedup vs baseline: 2.5207x; 1.2261x over previous
#include <cuda_runtime.h>

// ---------------------------------------------------------------------------
// RgbNet, R6.
//  K1 encode: thread per (ray, level), 5 samples with register corner cache;
//             weight transpose piggybacked. Writes g_feat[120][16384].
//  K2 mlp:    256 thr / 8 warps / 64 rays per block; warp = 8 outputs x
//             64 rays (lane owns ray pair 2*lane, 2*lane+1). Per k:
//             1 LDS.64 act + 2 broadcast LDS.128 weights -> 512 MACs.
//             96.8KB smem -> 2 blocks/SM, 256 blocks = one wave.
// ---------------------------------------------------------------------------

namespace {
constexpr int NRAYS   = 16384;
constexpr int NSAMP   = 300;
constexpr unsigned HSIZE = 1u << 19;
constexpr unsigned HMASK = HSIZE - 1u;
constexpr int WSTAGE  = 120 * 64 + 64 * 64 + 64 * 64;   // 15872 floats

constexpr int ENC_THREADS = 256;
constexpr int ENC_TASKS   = NRAYS * 6;
constexpr int ENC_BLOCKS  = ENC_TASKS / ENC_THREADS;     // 384

constexpr int MLP_THREADS = 256;     // 8 warps
constexpr int MLP_RPB     = 64;      // rays per block
constexpr int MLP_BLOCKS  = NRAYS / MLP_RPB;             // 256

// K2 shared layout (float offsets)
constexpr int OFF_W1T = 0;                    // [120][64]
constexpr int OFF_W2T = OFF_W1T + 120 * 64;   // [64][64]
constexpr int OFF_W3T = OFF_W2T + 64 * 64;    // [64][64]
constexpr int OFF_W4  = OFF_W3T + 64 * 64;    // [3][64]
constexpr int OFF_B1  = OFF_W4 + 192;
constexpr int OFF_B2  = OFF_B1 + 64;
constexpr int OFF_B3  = OFF_B2 + 64;
constexpr int OFF_B4  = OFF_B3 + 64;          // 4
constexpr int OFF_HA  = OFF_B4 + 4;           // [64][64]
constexpr int OFF_HB  = OFF_HA + 64 * 64;     // [64][64]
constexpr int SH_FLOATS = OFF_HB + 64 * 64;   // 24452 floats = 97808 B
}

__device__ float g_Wt[WSTAGE];            // [W1t | W2t | W3t], each [k][o]
__device__ float g_feat[120 * NRAYS];     // [k][ray]

// ---- fp32x2 helpers -------------------------------------------------------
__device__ __forceinline__ unsigned long long pack2(float v) {
    unsigned long long r;
    asm("mov.b64 %0, {%1, %1};" : "=l"(r) : "f"(v));
    return r;
}
__device__ __forceinline__ float2 unpack2(unsigned long long v) {
    float2 r;
    asm("mov.b64 {%0, %1}, %2;" : "=f"(r.x), "=f"(r.y) : "l"(v));
    return r;
}
#define FMA2(acc, a, b) \
    asm("fma.rn.f32x2 %0, %1, %2, %0;" : "+l"(acc) : "l"(a), "l"(b))

// ===========================================================================
// Kernel 1: encoding, thread per (ray, level), 5 samples with corner cache
// ===========================================================================
__global__ __launch_bounds__(ENC_THREADS)
void encode_kernel(const float* __restrict__ x,       // [N,4]
                   const int*   __restrict__ ifirst,  // [N]
                   const float* __restrict__ emb,     // [6,2^19,4]
                   const float* __restrict__ W1,
                   const float* __restrict__ W2,
                   const float* __restrict__ W3)
{
    const int t = blockIdx.x * ENC_THREADS + threadIdx.x;

    if (t < WSTAGE) {
        float v;
        if (t < 7680) {
            int k = t >> 6, o = t & 63;
            v = W1[o * 120 + k];
        } else if (t < 11776) {
            int j = t - 7680; int k = j >> 6, o = j & 63;
            v = W2[o * 64 + k];
        } else {
            int j = t - 11776; int k = j >> 6, o = j & 63;
            v = W3[o * 64 + k];
        }
        g_Wt[t] = v;
    }

    const int ray = t & (NRAYS - 1);
    const int l   = t >> 14;                 // 0..5, uniform per warp

    const float4 xr  = __ldg(reinterpret_cast<const float4*>(x) + ray);
    const int    if0 = __ldg(ifirst + ray);

    const int   R   = 4 << l;
    const float fR  = (float)R;
    const int   Rp1 = R + 1;
    const float4* __restrict__ tab =
        reinterpret_cast<const float4*>(emb) + (size_t)l * HSIZE;

    int    prev_key = -1;
    float4 cc[8];

    #pragma unroll
    for (int s = 0; s < 5; s++) {
        int sc = if0 + s - 2;
        sc = sc < 0 ? 0 : (sc > NSAMP - 1 ? NSAMP - 1 : sc);
        const float tt  = (float)sc * (1.0f / 299.0f);
        const float omt = 1.0f - tt;
        const float px = xr.x * omt + xr.z * tt;
        const float py = xr.y * omt + xr.w * tt;
        const float pz = tt;

        const float fx = px * fR, fy = py * fR, fz = pz * fR;
        const float flx = floorf(fx), fly = floorf(fy), flz = floorf(fz);
        const int ix = (int)flx, iy = (int)fly, iz = (int)flz;
        const float wx = fx - flx, wy = fy - fly, wz = fz - flz;

        const int key = ix | (iy << 10) | (iz << 20);
        if (key != prev_key) {
            prev_key = key;
            #pragma unroll
            for (int c = 0; c < 8; c++) {
                const int bx = (c >> 2) & 1, by = (c >> 1) & 1, bz = c & 1;
                int cx = ix + bx; cx = cx > R ? R : cx;
                int cy = iy + by; cy = cy > R ? R : cy;
                int cz = iz + bz; cz = cz > R ? R : cz;
                const unsigned id_dense =
                    (unsigned)(cx + cy * Rp1 + cz * Rp1 * Rp1);
                const unsigned id_hash =
                    ((unsigned)cx ^ ((unsigned)cy * 2654435761u)
                                 ^ ((unsigned)cz * 805459861u)) & HMASK;
                const unsigned idx = (l == 5) ? id_hash : id_dense;
                cc[c] = __ldg(tab + idx);
            }
        }

        float ax = 0.f, ay = 0.f, az = 0.f, aw = 0.f;
        #pragma unroll
        for (int c = 0; c < 8; c++) {
            const int bx = (c >> 2) & 1, by = (c >> 1) & 1, bz = c & 1;
            const float wgt = (bx ? wx : 1.0f - wx)
                            * (by ? wy : 1.0f - wy)
                            * (bz ? wz : 1.0f - wz);
            ax = fmaf(wgt, cc[c].x, ax);
            ay = fmaf(wgt, cc[c].y, ay);
            az = fmaf(wgt, cc[c].z, az);
            aw = fmaf(wgt, cc[c].w, aw);
        }

        const int kb = (s * 6 + l) * 4;
        g_feat[(size_t)(kb + 0) * NRAYS + ray] = ax;
        g_feat[(size_t)(kb + 1) * NRAYS + ray] = ay;
        g_feat[(size_t)(kb + 2) * NRAYS + ray] = az;
        g_feat[(size_t)(kb + 3) * NRAYS + ray] = aw;
    }
}

// ===========================================================================
// Kernel 2: MLP. 8 warps; warp = 8 outputs x 64 rays (2 rays per lane).
// ===========================================================================

__device__ __forceinline__ void layer_hidden2(const float* __restrict__ Wt,
                                              const float* __restrict__ bs,
                                              const float* __restrict__ actIn,
                                              float*       __restrict__ actOut,
                                              int obase, int lane) {
    unsigned long long accA[4], accB[4];
    {
        const ulonglong2* bp =
            reinterpret_cast<const ulonglong2*>(bs + obase);
        const ulonglong2 b0 = bp[0], b1 = bp[1];
        accA[0] = b0.x; accA[1] = b0.y; accA[2] = b1.x; accA[3] = b1.y;
        accB[0] = b0.x; accB[1] = b0.y; accB[2] = b1.x; accB[3] = b1.y;
    }
    const int rcol = 2 * lane;
    #pragma unroll 8
    for (int k = 0; k < 64; k++) {
        const float2 f =
            *reinterpret_cast<const float2*>(actIn + k * 64 + rcol);
        const unsigned long long fa = pack2(f.x);
        const unsigned long long fb = pack2(f.y);
        const ulonglong2* wp =
            reinterpret_cast<const ulonglong2*>(Wt + k * 64 + obase);
        const ulonglong2 w0 = wp[0], w1 = wp[1];
        FMA2(accA[0], fa, w0.x); FMA2(accB[0], fb, w0.x);
        FMA2(accA[1], fa, w0.y); FMA2(accB[1], fb, w0.y);
        FMA2(accA[2], fa, w1.x); FMA2(accB[2], fb, w1.x);
        FMA2(accA[3], fa, w1.y); FMA2(accB[3], fb, w1.y);
    }
    #pragma unroll
    for (int p = 0; p < 4; p++) {
        const float2 a = unpack2(accA[p]);   // outs (2p,2p+1) @ ray rcol
        const float2 b = unpack2(accB[p]);   // outs (2p,2p+1) @ ray rcol+1
        *reinterpret_cast<float2*>(actOut + (obase + 2 * p) * 64 + rcol) =
            make_float2(fmaxf(a.x, 0.0f), fmaxf(b.x, 0.0f));
        *reinterpret_cast<float2*>(actOut + (obase + 2 * p + 1) * 64 + rcol) =
            make_float2(fmaxf(a.y, 0.0f), fmaxf(b.y, 0.0f));
    }
}

__global__ __launch_bounds__(MLP_THREADS, 2)
void mlp_kernel(const float* __restrict__ b1, const float* __restrict__ b2,
                const float* __restrict__ b3,
                const float* __restrict__ W4, const float* __restrict__ b4,
                float* __restrict__ out)
{
    extern __shared__ float sh[];
    const int tid = threadIdx.x;

    // ---- stage pre-transposed weights (coalesced float4) -------------------
    {
        const float4* src = reinterpret_cast<const float4*>(g_Wt);
        float4*       dst = reinterpret_cast<float4*>(sh);
        #pragma unroll
        for (int i = tid; i < WSTAGE / 4; i += MLP_THREADS) dst[i] = src[i];
    }
    if (tid < 192) sh[OFF_W4 + tid] = __ldg(W4 + tid);
    if (tid < 64) {
        sh[OFF_B1 + tid] = __ldg(b1 + tid);
        sh[OFF_B2 + tid] = __ldg(b2 + tid);
        sh[OFF_B3 + tid] = __ldg(b3 + tid);
    }
    if (tid < 4) sh[OFF_B4 + tid] = (tid < 3) ? __ldg(b4 + tid) : 0.0f;
    __syncthreads();

    const int lane  = tid & 31;
    const int warp  = tid >> 5;                 // 0..7
    const int obase = warp * 8;                 // 8-output chunk
    const int rcol  = 2 * lane;                 // ray pair within block
    const int ray0  = blockIdx.x * MLP_RPB + rcol;

    float* hA = sh + OFF_HA;
    float* hB = sh + OFF_HB;

    // ---------------- layer 1: 120 -> 64, feats (float2) from g_feat --------
    {
        unsigned long long accA[4], accB[4];
        {
            const ulonglong2* bp =
                reinterpret_cast<const ulonglong2*>(sh + OFF_B1 + obase);
            const ulonglong2 b0 = bp[0], bb1 = bp[1];
            accA[0] = b0.x; accA[1] = b0.y; accA[2] = bb1.x; accA[3] = bb1.y;
            accB[0] = b0.x; accB[1] = b0.y; accB[2] = bb1.x; accB[3] = bb1.y;
        }
        const float* __restrict__ Wt = sh + OFF_W1T;

        float2 fbuf[8];
        #pragma unroll
        for (int j = 0; j < 8; j++)
            fbuf[j] = __ldg(reinterpret_cast<const float2*>(
                          &g_feat[(size_t)j * NRAYS + ray0]));

        for (int kb = 0; kb < 120; kb += 8) {
            float2 fc[8];
            #pragma unroll
            for (int j = 0; j < 8; j++) fc[j] = fbuf[j];
            if (kb + 8 < 120) {
                #pragma unroll
                for (int j = 0; j < 8; j++)
                    fbuf[j] = __ldg(reinterpret_cast<const float2*>(
                                  &g_feat[(size_t)(kb + 8 + j) * NRAYS + ray0]));
            }
            #pragma unroll
            for (int j = 0; j < 8; j++) {
                const unsigned long long fa = pack2(fc[j].x);
                const unsigned long long fb = pack2(fc[j].y);
                const ulonglong2* wp = reinterpret_cast<const ulonglong2*>(
                    Wt + (kb + j) * 64 + obase);
                const ulonglong2 w0 = wp[0], w1 = wp[1];
                FMA2(accA[0], fa, w0.x); FMA2(accB[0], fb, w0.x);
                FMA2(accA[1], fa, w0.y); FMA2(accB[1], fb, w0.y);
                FMA2(accA[2], fa, w1.x); FMA2(accB[2], fb, w1.x);
                FMA2(accA[3], fa, w1.y); FMA2(accB[3], fb, w1.y);
            }
        }
        #pragma unroll
        for (int p = 0; p < 4; p++) {
            const float2 a = unpack2(accA[p]);
            const float2 b = unpack2(accB[p]);
            *reinterpret_cast<float2*>(hA + (obase + 2 * p) * 64 + rcol) =
                make_float2(fmaxf(a.x, 0.0f), fmaxf(b.x, 0.0f));
            *reinterpret_cast<float2*>(hA + (obase + 2 * p + 1) * 64 + rcol) =
                make_float2(fmaxf(a.y, 0.0f), fmaxf(b.y, 0.0f));
        }
    }
    __syncthreads();

    // ---------------- layer 2: hA -> hB --------------------------------------
    layer_hidden2(sh + OFF_W2T, sh + OFF_B2, hA, hB, obase, lane);
    __syncthreads();

    // ---------------- layer 3: hB -> hA --------------------------------------
    layer_hidden2(sh + OFF_W3T, sh + OFF_B3, hB, hA, obase, lane);
    __syncthreads();

    // ---------------- layer 4: 64 -> 3, threads 0..63 ------------------------
    if (tid < MLP_RPB) {
        const float* W4s = sh + OFF_W4;
        float a0 = sh[OFF_B4 + 0], a1 = sh[OFF_B4 + 1], a2 = sh[OFF_B4 + 2];
        #pragma unroll 8
        for (int k = 0; k < 64; k++) {
            const float hv = hA[k * 64 + tid];
            a0 = fmaf(hv, W4s[k],       a0);
            a1 = fmaf(hv, W4s[64 + k],  a1);
            a2 = fmaf(hv, W4s[128 + k], a2);
        }
        float* o = out + (size_t)(blockIdx.x * MLP_RPB + tid) * 3;
        o[0] = a0; o[1] = a1; o[2] = a2;
    }
}

extern "C" void kernel_launch(void* const* d_in, const int* in_sizes, int n_in,
                              void* d_out, int out_size) {
    const float* x    = (const float*)d_in[0];
    const int*   idxf = (const int*)  d_in[1];
    const float* emb  = (const float*)d_in[2];
    const float* W1   = (const float*)d_in[3];
    const float* b1   = (const float*)d_in[4];
    const float* W2   = (const float*)d_in[5];
    const float* b2   = (const float*)d_in[6];
    const float* W3   = (const float*)d_in[7];
    const float* b3   = (const float*)d_in[8];
    const float* W4   = (const float*)d_in[9];
    const float* b4   = (const float*)d_in[10];
    float* out = (float*)d_out;

    encode_kernel<<<ENC_BLOCKS, ENC_THREADS>>>(x, idxf, emb, W1, W2, W3);

    const size_t shbytes = (size_t)SH_FLOATS * sizeof(float);   // 97808 B
    cudaFuncSetAttribute(mlp_kernel,
                         cudaFuncAttributeMaxDynamicSharedMemorySize,
                         (int)shbytes);
    mlp_kernel<<<MLP_BLOCKS, MLP_THREADS, shbytes>>>(b1, b2, b3, W4, b4, out);
}